// round 1
// baseline (speedup 1.0000x reference)
#include <cuda_runtime.h>

// 3D spatial correlation sampler, patch=7, dil=1, k=1, s=1, pad=0
// in1,in2: [B=2, C=32, D=32, H=32, W=32] fp32
// out: [B, 7, 7, 7, D, H, W] fp32
//
// Block = (b, d, h-tile of 8). Stage in1 tile + per-od in2 slab (w/h halo,
// zero-padded) in shared memory; thread computes 7(pw) x 4(w) outputs per
// (od, oh) with a 12-float sliding window -> 28 FFMA per 4 LDS.128.

#define BB 2
#define CC 32
#define DD 32
#define HH 32
#define WW 32
#define PP 7
#define TH 8              // h rows per block
#define NTHREADS 64       // 8 h-rows x 8 w-quads

#define IN1_SZ (CC * TH * WW)            // 8192 floats (32 KB)
#define SLAB_ROWS (TH + 6)               // 14
#define SLAB_PITCH 40                    // 38 valid (w: -3..34 at s=w+4) + pad
#define SLAB_SZ (CC * SLAB_ROWS * SLAB_PITCH)  // 17920 floats (71.7 KB)
#define SMEM_FLOATS (IN1_SZ + SLAB_SZ)   // 26112 floats = 104448 bytes

__global__ __launch_bounds__(NTHREADS)
void corr3d_kernel(const float* __restrict__ in1,
                   const float* __restrict__ in2,
                   float* __restrict__ out)
{
    extern __shared__ float sm[];
    float* in1s = sm;             // [c][h][w]  : c*256 + h*32 + w
    float* slab = sm + IN1_SZ;    // [c][r][s]  : c*560 + r*40 + s,  s = w+4

    const int bx = blockIdx.x;        // 256 blocks: b(2) x d(32) x hq(4)
    const int hq = bx & 3;
    const int d  = (bx >> 2) & 31;
    const int b  = bx >> 7;
    const int h0 = hq * TH;

    const int t  = threadIdx.x;
    const int wi = t & 7;
    const int w0 = wi * 4;
    const int hl = t >> 3;            // 0..7

    // ---- stage in1 tile: 2048 float4 slots over 64 threads ----
    {
        const float* g = in1 + (size_t)(b * CC * DD + d) * (HH * WW);
        #pragma unroll 4
        for (int i = 0; i < 32; i++) {
            int slot = i * NTHREADS + t;          // 0..2047
            int c    = slot >> 6;                 // 64 float4 per c
            int rem  = slot & 63;
            int hh   = rem >> 3;
            int w4   = (rem & 7) * 4;
            float4 v = *(const float4*)(g + (size_t)c * (DD * HH * WW)
                                          + (h0 + hh) * WW + w4);
            *(float4*)(in1s + c * (TH * WW) + hh * WW + w4) = v;
        }
    }
    // (in1 readiness is covered by the slab-staging __syncthreads below)

    const float* in2b = in2 + (size_t)(b * CC * DD) * (HH * WW);

    for (int od = 0; od < PP; od++) {
        const int z = d + od - 3;               // uniform across block
        if (z < 0 || z >= DD) {
            // whole d-plane out of range -> zeros for all (oh,pw)
            const float4 z4 = make_float4(0.f, 0.f, 0.f, 0.f);
            for (int oh = 0; oh < PP; oh++) {
                #pragma unroll
                for (int pw = 0; pw < PP; pw++) {
                    size_t o = (size_t)(((b * PP + od) * PP + oh) * PP + pw)
                                 * (DD * HH * WW)
                             + (size_t)d * (HH * WW) + (h0 + hl) * WW + w0;
                    *(float4*)(out + o) = z4;
                }
            }
            continue;
        }

        __syncthreads();   // previous od's readers are done with slab

        // ---- stage slab: 32c x 14r x 10 float4-slots = 4480 slots ----
        #pragma unroll 2
        for (int i = 0; i < 70; i++) {
            int slot = i * NTHREADS + t;
            int c    = slot / 140;
            int rem  = slot - c * 140;
            int r    = rem / 10;
            int s4   = rem - r * 10;
            int hg   = h0 + r - 3;
            float4 v = make_float4(0.f, 0.f, 0.f, 0.f);
            if (s4 >= 1 && s4 <= 8 && hg >= 0 && hg < HH) {
                int wb = (s4 - 1) * 4;
                v = *(const float4*)(in2b + (size_t)c * (DD * HH * WW)
                                          + (size_t)z * (HH * WW)
                                          + hg * WW + wb);
            }
            *(float4*)(slab + c * (SLAB_ROWS * SLAB_PITCH) + r * SLAB_PITCH + s4 * 4) = v;
        }
        __syncthreads();

        // ---- compute ----
        for (int oh = 0; oh < PP; oh++) {
            float acc[PP][4];
            #pragma unroll
            for (int pw = 0; pw < PP; pw++) {
                acc[pw][0] = 0.f; acc[pw][1] = 0.f;
                acc[pw][2] = 0.f; acc[pw][3] = 0.f;
            }

            const float* ap = in1s + hl * WW + w0;
            const float* bp = slab + (hl + oh) * SLAB_PITCH + w0;

            #pragma unroll 4
            for (int c = 0; c < CC; c++) {
                float4 a  = *(const float4*)ap;
                float4 q0 = *(const float4*)(bp);
                float4 q1 = *(const float4*)(bp + 4);
                float4 q2 = *(const float4*)(bp + 8);
                float bb[12] = {q0.x, q0.y, q0.z, q0.w,
                                q1.x, q1.y, q1.z, q1.w,
                                q2.x, q2.y, q2.z, q2.w};
                // out w = w0+i, in2 w = w0+i+pw-3, slab s = w+4 => bb[i+pw+1]
                #pragma unroll
                for (int pw = 0; pw < PP; pw++) {
                    acc[pw][0] += a.x * bb[pw + 1];
                    acc[pw][1] += a.y * bb[pw + 2];
                    acc[pw][2] += a.z * bb[pw + 3];
                    acc[pw][3] += a.w * bb[pw + 4];
                }
                ap += TH * WW;
                bp += SLAB_ROWS * SLAB_PITCH;
            }

            #pragma unroll
            for (int pw = 0; pw < PP; pw++) {
                size_t o = (size_t)(((b * PP + od) * PP + oh) * PP + pw)
                             * (DD * HH * WW)
                         + (size_t)d * (HH * WW) + (h0 + hl) * WW + w0;
                *(float4*)(out + o) =
                    make_float4(acc[pw][0], acc[pw][1], acc[pw][2], acc[pw][3]);
            }
        }
    }
}

extern "C" void kernel_launch(void* const* d_in, const int* in_sizes, int n_in,
                              void* d_out, int out_size)
{
    const float* in1 = (const float*)d_in[0];
    const float* in2 = (const float*)d_in[1];
    float* out = (float*)d_out;

    cudaFuncSetAttribute(corr3d_kernel,
                         cudaFuncAttributeMaxDynamicSharedMemorySize,
                         SMEM_FLOATS * sizeof(float));

    dim3 grid(BB * DD * 4);   // 256 blocks
    dim3 block(NTHREADS);
    corr3d_kernel<<<grid, block, SMEM_FLOATS * sizeof(float)>>>(in1, in2, out);
}

// round 2
// speedup vs baseline: 1.1348x; 1.1348x over previous
#include <cuda_runtime.h>

// 3D spatial correlation sampler, patch=7, dil=1, k=1, s=1, pad=0
// in1,in2: [B=2, C=32, D=32, H=32, W=32] fp32
// out: [B, 7, 7, 7, D, H, W] fp32
//
// Grid = (b, d, hq, od) -> 1792 blocks. Block = 224 threads = 7 warps;
// warp w computes oh = w. Thread owns (h-row, 8 consecutive w).
// in2 slab (1 d-plane, h/w halo, zero-padded) staged in smem (pitch 44,
// bank-conflict-free); in1 read straight from L1 (shared across warps).

#define BB 2
#define CC 32
#define DD 32
#define HH 32
#define WW 32
#define PP 7
#define TH 8               // h rows per block
#define NTHREADS 224       // 7 warps (one per oh)

#define SLAB_ROWS (TH + 6)             // 14
#define SLAB_PITCH 44                  // row step mod 32 banks = 12 -> conflict-free
#define SLAB_SZ (CC * SLAB_ROWS * SLAB_PITCH)   // 19712 floats = 78848 B

__global__ __launch_bounds__(NTHREADS)
void corr3d_kernel(const float* __restrict__ in1,
                   const float* __restrict__ in2,
                   float* __restrict__ out)
{
    extern __shared__ float slab[];    // [c][r][s] : c*616 + r*44 + s, s = w+4

    // grid decode: bx = ((b*32 + d)*4 + hq)*7 + od
    int bx = blockIdx.x;
    const int od = bx % 7;   bx /= 7;
    const int hq = bx & 3;   bx >>= 2;
    const int d  = bx & 31;
    const int b  = bx >> 5;
    const int h0 = hq * TH;

    const int t    = threadIdx.x;
    const int lane = t & 31;
    const int oh   = t >> 5;           // warp id = oh (0..6)
    const int hl   = lane & 7;
    const int wi   = lane >> 3;        // 0..3
    const int w0   = wi * 8;

    const int z = d + od - 3;          // uniform per block
    const bool zvalid = (z >= 0) && (z < DD);

    float acc[PP][8];
    #pragma unroll
    for (int pw = 0; pw < PP; pw++)
        #pragma unroll
        for (int i = 0; i < 8; i++) acc[pw][i] = 0.f;

    if (zvalid) {
        // ---- stage slab: 32c x 14r x 10 float4 slots = 4480 over 224 thr ----
        const float* in2p = in2 + ((size_t)(b * CC * DD) + z) * (HH * WW);
        #pragma unroll 2
        for (int i = 0; i < 20; i++) {
            int slot = i * NTHREADS + t;
            int c    = slot / 140;
            int rem  = slot - c * 140;
            int r    = rem / 10;
            int s4   = rem - r * 10;
            int hg   = h0 + r - 3;
            float4 v = make_float4(0.f, 0.f, 0.f, 0.f);
            if (s4 >= 1 && s4 <= 8 && hg >= 0 && hg < HH) {
                v = *(const float4*)(in2p + (size_t)c * (DD * HH * WW)
                                          + hg * WW + (s4 - 1) * 4);
            }
            *(float4*)(slab + c * (SLAB_ROWS * SLAB_PITCH) + r * SLAB_PITCH + s4 * 4) = v;
        }
        __syncthreads();

        // ---- compute: acc[pw][i] += in1[c,h,w0+i] * slab[c, hl+oh, w0+i+pw+1] ----
        const float* ap = in1 + (size_t)(b * CC * DD + d) * (HH * WW)
                              + (h0 + hl) * WW + w0;
        const float* bp = slab + (hl + oh) * SLAB_PITCH + w0;

        #pragma unroll 2
        for (int c = 0; c < CC; c++) {
            float4 a0 = *(const float4*)(ap);
            float4 a1 = *(const float4*)(ap + 4);
            float4 q0 = *(const float4*)(bp);
            float4 q1 = *(const float4*)(bp + 4);
            float4 q2 = *(const float4*)(bp + 8);
            float4 q3 = *(const float4*)(bp + 12);
            float av[8] = {a0.x, a0.y, a0.z, a0.w, a1.x, a1.y, a1.z, a1.w};
            float bb[16] = {q0.x, q0.y, q0.z, q0.w, q1.x, q1.y, q1.z, q1.w,
                            q2.x, q2.y, q2.z, q2.w, q3.x, q3.y, q3.z, q3.w};
            // out w = w0+i, in2 w = w0+i+pw-3, s = w+4 -> bb[i+pw+1]
            #pragma unroll
            for (int pw = 0; pw < PP; pw++)
                #pragma unroll
                for (int i = 0; i < 8; i++)
                    acc[pw][i] += av[i] * bb[i + pw + 1];

            ap += DD * HH * WW;
            bp += SLAB_ROWS * SLAB_PITCH;
        }
    }

    // ---- store (zeros if z OOB) ----
    size_t obase = (size_t)(((b * PP + od) * PP + oh) * PP) * (DD * HH * WW)
                 + (size_t)d * (HH * WW) + (h0 + hl) * WW + w0;
    #pragma unroll
    for (int pw = 0; pw < PP; pw++) {
        float* o = out + obase + (size_t)pw * (DD * HH * WW);
        *(float4*)(o)     = make_float4(acc[pw][0], acc[pw][1], acc[pw][2], acc[pw][3]);
        *(float4*)(o + 4) = make_float4(acc[pw][4], acc[pw][5], acc[pw][6], acc[pw][7]);
    }
}

extern "C" void kernel_launch(void* const* d_in, const int* in_sizes, int n_in,
                              void* d_out, int out_size)
{
    const float* in1 = (const float*)d_in[0];
    const float* in2 = (const float*)d_in[1];
    float* out = (float*)d_out;

    cudaFuncSetAttribute(corr3d_kernel,
                         cudaFuncAttributeMaxDynamicSharedMemorySize,
                         SLAB_SZ * sizeof(float));

    dim3 grid(BB * DD * 4 * PP);   // 1792 blocks
    dim3 block(NTHREADS);
    corr3d_kernel<<<grid, block, SLAB_SZ * sizeof(float)>>>(in1, in2, out);
}

// round 3
// speedup vs baseline: 2.0746x; 1.8283x over previous
#include <cuda_runtime.h>

// 3D spatial correlation sampler, patch=7, dil=1, k=1, s=1, pad=0
// in1,in2: [B=2, C=32, D=32, H=32, W=32] fp32
// out: [B, 7, 7, 7, D, H, W] fp32
//
// Grid = (b, d, hq, od) -> 1792 blocks; 224 threads = 7 warps, warp = oh.
// Channels processed in 2 chunks of 16; per chunk both in1 tile and in2
// slab are staged in smem with conflict-free pitches (36 / 44).
// Thread owns (h-row, 8 consecutive w) -> 56 FFMA per 6 LDS.128.

#define BB 2
#define CC 32
#define DD 32
#define HH 32
#define WW 32
#define PP 7
#define TH 8
#define NTHREADS 224
#define CCHUNK 16

#define IN1_PITCH 36                    // step mod 32 = 4 -> conflict-free
#define IN1C_SZ (CCHUNK * TH * IN1_PITCH)        // 4608 floats
#define SLAB_ROWS (TH + 6)              // 14
#define SLAB_PITCH 44                   // step mod 32 = 12 -> conflict-free
#define SLABC_SZ (CCHUNK * SLAB_ROWS * SLAB_PITCH)  // 9856 floats
#define SMEM_FLOATS (IN1C_SZ + SLABC_SZ)            // 14464 floats = 57856 B

__global__ __launch_bounds__(NTHREADS, 2)
void corr3d_kernel(const float* __restrict__ in1,
                   const float* __restrict__ in2,
                   float* __restrict__ out)
{
    extern __shared__ float sm[];
    float* in1s = sm;               // [c][h][36]
    float* slab = sm + IN1C_SZ;     // [c][r][44], s = w+4

    int bx = blockIdx.x;            // ((b*32 + d)*4 + hq)*7 + od
    const int od = bx % 7;   bx /= 7;
    const int hq = bx & 3;   bx >>= 2;
    const int d  = bx & 31;
    const int b  = bx >> 5;
    const int h0 = hq * TH;

    const int t    = threadIdx.x;
    const int lane = t & 31;
    const int oh   = t >> 5;        // warp id = oh
    const int hl   = lane & 7;
    const int wi   = lane >> 3;
    const int w0   = wi * 8;

    const int z = d + od - 3;       // uniform per block
    const bool zvalid = (z >= 0) && (z < DD);

    float acc[PP][8];
    #pragma unroll
    for (int pw = 0; pw < PP; pw++)
        #pragma unroll
        for (int i = 0; i < 8; i++) acc[pw][i] = 0.f;

    if (zvalid) {
        for (int cc = 0; cc < CC; cc += CCHUNK) {
            __syncthreads();   // previous chunk fully consumed

            // ---- stage in1 chunk: 16c x 8h x 8 float4 = 1024 slots ----
            {
                const float* g = in1 + ((size_t)(b * CC + cc) * DD + d) * (HH * WW);
                #pragma unroll
                for (int i = 0; i < 5; i++) {
                    int slot = i * NTHREADS + t;
                    if (slot < CCHUNK * TH * 8) {
                        int c   = slot >> 6;
                        int rem = slot & 63;
                        int hh  = rem >> 3;
                        int w4  = (rem & 7) * 4;
                        float4 v = *(const float4*)(g + (size_t)c * (DD * HH * WW)
                                                      + (h0 + hh) * WW + w4);
                        *(float4*)(in1s + c * (TH * IN1_PITCH) + hh * IN1_PITCH + w4) = v;
                    }
                }
            }

            // ---- stage slab chunk: 16c x 14r x 10 float4 = 2240 slots ----
            {
                const float* g = in2 + ((size_t)(b * CC + cc) * DD + z) * (HH * WW);
                #pragma unroll
                for (int i = 0; i < 10; i++) {
                    int slot = i * NTHREADS + t;
                    int c    = slot / 140;
                    int rem  = slot - c * 140;
                    int r    = rem / 10;
                    int s4   = rem - r * 10;
                    int hg   = h0 + r - 3;
                    float4 v = make_float4(0.f, 0.f, 0.f, 0.f);
                    if (s4 >= 1 && s4 <= 8 && hg >= 0 && hg < HH) {
                        v = *(const float4*)(g + (size_t)c * (DD * HH * WW)
                                               + hg * WW + (s4 - 1) * 4);
                    }
                    *(float4*)(slab + c * (SLAB_ROWS * SLAB_PITCH)
                                    + r * SLAB_PITCH + s4 * 4) = v;
                }
            }
            __syncthreads();

            // ---- compute 16 channels ----
            const float* ap = in1s + hl * IN1_PITCH + w0;
            const float* bp = slab + (hl + oh) * SLAB_PITCH + w0;

            #pragma unroll 2
            for (int c = 0; c < CCHUNK; c++) {
                float4 a0 = *(const float4*)(ap);
                float4 a1 = *(const float4*)(ap + 4);
                float4 q0 = *(const float4*)(bp);
                float4 q1 = *(const float4*)(bp + 4);
                float4 q2 = *(const float4*)(bp + 8);
                float4 q3 = *(const float4*)(bp + 12);
                float av[8]  = {a0.x, a0.y, a0.z, a0.w, a1.x, a1.y, a1.z, a1.w};
                float bb[16] = {q0.x, q0.y, q0.z, q0.w, q1.x, q1.y, q1.z, q1.w,
                                q2.x, q2.y, q2.z, q2.w, q3.x, q3.y, q3.z, q3.w};
                // out w = w0+i, in2 w = w0+i+pw-3, s = w+4 -> bb[i+pw+1]
                #pragma unroll
                for (int pw = 0; pw < PP; pw++)
                    #pragma unroll
                    for (int i = 0; i < 8; i++)
                        acc[pw][i] += av[i] * bb[i + pw + 1];

                ap += TH * IN1_PITCH;
                bp += SLAB_ROWS * SLAB_PITCH;
            }
        }
    }

    // ---- store (zeros if z OOB) ----
    size_t obase = (size_t)(((b * PP + od) * PP + oh) * PP) * (DD * HH * WW)
                 + (size_t)d * (HH * WW) + (h0 + hl) * WW + w0;
    #pragma unroll
    for (int pw = 0; pw < PP; pw++) {
        float* o = out + obase + (size_t)pw * (DD * HH * WW);
        *(float4*)(o)     = make_float4(acc[pw][0], acc[pw][1], acc[pw][2], acc[pw][3]);
        *(float4*)(o + 4) = make_float4(acc[pw][4], acc[pw][5], acc[pw][6], acc[pw][7]);
    }
}

extern "C" void kernel_launch(void* const* d_in, const int* in_sizes, int n_in,
                              void* d_out, int out_size)
{
    const float* in1 = (const float*)d_in[0];
    const float* in2 = (const float*)d_in[1];
    float* out = (float*)d_out;

    cudaFuncSetAttribute(corr3d_kernel,
                         cudaFuncAttributeMaxDynamicSharedMemorySize,
                         SMEM_FLOATS * sizeof(float));

    dim3 grid(BB * DD * 4 * PP);   // 1792
    dim3 block(NTHREADS);
    corr3d_kernel<<<grid, block, SMEM_FLOATS * sizeof(float)>>>(in1, in2, out);
}

// round 4
// speedup vs baseline: 2.4096x; 1.1614x over previous
#include <cuda_runtime.h>
#include <cstdint>

// 3D spatial correlation sampler, patch=7, dil=1, k=1, s=1, pad=0
// in1,in2: [B=2, C=32, D=32, H=32, W=32] fp32
// out: [B, 7, 7, 7, D, H, W] fp32
//
// Grid = (b, d, hq, od) -> 1792 blocks; 224 threads = 7 warps, warp = oh.
// Channels in 4 chunks of 8, double-buffered with cp.async (zfill halo).
// Thread owns (h-row, 8 consecutive w) -> 56 FFMA per 6 LDS.128.

#define BB 2
#define CC 32
#define DD 32
#define HH 32
#define WW 32
#define PP 7
#define TH 8
#define NTHREADS 224
#define CCHUNK 8
#define NCHUNK (CC / CCHUNK)     // 4

#define IN1_PITCH 36                               // step mod 32 = 4 -> conflict-free
#define IN1C_SZ (CCHUNK * TH * IN1_PITCH)          // 2304 floats
#define SLAB_ROWS (TH + 6)                         // 14
#define SLAB_PITCH 44                              // step mod 32 = 12 -> conflict-free
#define SLABC_SZ (CCHUNK * SLAB_ROWS * SLAB_PITCH) // 4928 floats
#define BUF_SZ (IN1C_SZ + SLABC_SZ)                // 7232 floats
#define SMEM_FLOATS (2 * BUF_SZ)                   // 14464 floats = 57856 B

__device__ __forceinline__ void cp_async16(uint32_t dst, const void* src, int src_bytes) {
    asm volatile("cp.async.cg.shared.global [%0], [%1], 16, %2;\n"
                 :: "r"(dst), "l"(src), "r"(src_bytes));
}

__global__ __launch_bounds__(NTHREADS, 2)
void corr3d_kernel(const float* __restrict__ in1,
                   const float* __restrict__ in2,
                   float* __restrict__ out)
{
    extern __shared__ float sm[];   // 2 buffers: [in1 2304 | slab 4928] each

    int bx = blockIdx.x;            // ((b*32 + d)*4 + hq)*7 + od
    const int od = bx % 7;   bx /= 7;
    const int hq = bx & 3;   bx >>= 2;
    const int d  = bx & 31;
    const int b  = bx >> 5;
    const int h0 = hq * TH;

    const int t    = threadIdx.x;
    const int lane = t & 31;
    const int oh   = t >> 5;        // warp id = oh
    const int hl   = lane & 7;
    const int wi   = lane >> 3;
    const int w0   = wi * 8;

    const int z = d + od - 3;       // uniform per block
    const bool zvalid = (z >= 0) && (z < DD);

    float acc[PP][8];
    #pragma unroll
    for (int pw = 0; pw < PP; pw++)
        #pragma unroll
        for (int i = 0; i < 8; i++) acc[pw][i] = 0.f;

    if (zvalid) {
        const float* in1g = in1 + ((size_t)(b * CC) * DD + d) * (HH * WW);
        const float* in2g = in2 + ((size_t)(b * CC) * DD + z) * (HH * WW);
        const uint32_t smem_u32 = (uint32_t)__cvta_generic_to_shared(sm);

        // precompute this thread's staging slots (same for every chunk)
        // in1: 512 slots over 224 threads (slots t, t+224, t+448 if <512)
        // slab: 1120 slots over 224 threads (5 each, exact)

        // ---- stage one chunk into buffer `buf` via cp.async ----
        auto stage = [&](int chunk, int buf) {
            const float* g1 = in1g + (size_t)(chunk * CCHUNK) * (DD * HH * WW);
            const float* g2 = in2g + (size_t)(chunk * CCHUNK) * (DD * HH * WW);
            uint32_t base = smem_u32 + (uint32_t)(buf * BUF_SZ) * 4u;
            uint32_t in1b = base;
            uint32_t slabb = base + IN1C_SZ * 4u;

            #pragma unroll
            for (int i = 0; i < 3; i++) {
                int slot = i * NTHREADS + t;
                if (slot < CCHUNK * TH * 8) {
                    int c   = slot >> 6;
                    int rem = slot & 63;
                    int hh  = rem >> 3;
                    int w4  = (rem & 7) * 4;
                    cp_async16(in1b + (uint32_t)(c * (TH * IN1_PITCH)
                                                 + hh * IN1_PITCH + w4) * 4u,
                               g1 + (size_t)c * (DD * HH * WW) + (h0 + hh) * WW + w4,
                               16);
                }
            }
            #pragma unroll
            for (int i = 0; i < 5; i++) {
                int slot = i * NTHREADS + t;
                int c    = slot / 140;
                int rem  = slot - c * 140;
                int r    = rem / 10;
                int s4   = rem - r * 10;
                int hg   = h0 + r - 3;
                bool v   = (s4 >= 1) && (s4 <= 8) && (hg >= 0) && (hg < HH);
                const float* src = v ? (g2 + (size_t)c * (DD * HH * WW)
                                           + hg * WW + (s4 - 1) * 4)
                                     : g2;       // clamped dummy, zfilled
                cp_async16(slabb + (uint32_t)(c * (SLAB_ROWS * SLAB_PITCH)
                                              + r * SLAB_PITCH + s4 * 4) * 4u,
                           src, v ? 16 : 0);
            }
            asm volatile("cp.async.commit_group;\n" ::);
        };

        stage(0, 0);
        asm volatile("cp.async.wait_group 0;\n" ::);
        __syncthreads();

        for (int ch = 0; ch < NCHUNK; ch++) {
            if (ch + 1 < NCHUNK) stage(ch + 1, (ch + 1) & 1);

            const float* bufp = sm + (ch & 1) * BUF_SZ;
            const float* ap = bufp + hl * IN1_PITCH + w0;
            const float* bp = bufp + IN1C_SZ + (hl + oh) * SLAB_PITCH + w0;

            #pragma unroll 4
            for (int c = 0; c < CCHUNK; c++) {
                float4 a0 = *(const float4*)(ap);
                float4 a1 = *(const float4*)(ap + 4);
                float4 q0 = *(const float4*)(bp);
                float4 q1 = *(const float4*)(bp + 4);
                float4 q2 = *(const float4*)(bp + 8);
                float4 q3 = *(const float4*)(bp + 12);
                float av[8]  = {a0.x, a0.y, a0.z, a0.w, a1.x, a1.y, a1.z, a1.w};
                float bb[16] = {q0.x, q0.y, q0.z, q0.w, q1.x, q1.y, q1.z, q1.w,
                                q2.x, q2.y, q2.z, q2.w, q3.x, q3.y, q3.z, q3.w};
                // out w = w0+i, in2 w = w0+i+pw-3, s = w+4 -> bb[i+pw+1]
                #pragma unroll
                for (int pw = 0; pw < PP; pw++)
                    #pragma unroll
                    for (int i = 0; i < 8; i++)
                        acc[pw][i] += av[i] * bb[i + pw + 1];

                ap += TH * IN1_PITCH;
                bp += SLAB_ROWS * SLAB_PITCH;
            }

            if (ch + 1 < NCHUNK) {
                asm volatile("cp.async.wait_group 0;\n" ::);
                __syncthreads();   // next chunk ready; everyone done with this buf
            }
        }
    }

    // ---- store (zeros if z OOB) ----
    size_t obase = (size_t)(((b * PP + od) * PP + oh) * PP) * (DD * HH * WW)
                 + (size_t)d * (HH * WW) + (h0 + hl) * WW + w0;
    #pragma unroll
    for (int pw = 0; pw < PP; pw++) {
        float* o = out + obase + (size_t)pw * (DD * HH * WW);
        *(float4*)(o)     = make_float4(acc[pw][0], acc[pw][1], acc[pw][2], acc[pw][3]);
        *(float4*)(o + 4) = make_float4(acc[pw][4], acc[pw][5], acc[pw][6], acc[pw][7]);
    }
}

extern "C" void kernel_launch(void* const* d_in, const int* in_sizes, int n_in,
                              void* d_out, int out_size)
{
    const float* in1 = (const float*)d_in[0];
    const float* in2 = (const float*)d_in[1];
    float* out = (float*)d_out;

    cudaFuncSetAttribute(corr3d_kernel,
                         cudaFuncAttributeMaxDynamicSharedMemorySize,
                         SMEM_FLOATS * sizeof(float));

    dim3 grid(BB * DD * 4 * PP);   // 1792
    dim3 block(NTHREADS);
    corr3d_kernel<<<grid, block, SMEM_FLOATS * sizeof(float)>>>(in1, in2, out);
}